// round 15
// baseline (speedup 1.0000x reference)
#include <cuda_runtime.h>
#include <math.h>

#define PS 16
#define NB 32
#define IMGSZ (1024*1024)

__device__ __forceinline__ float clamp01(float x) {
    return fminf(fmaxf(x, 0.0f), 1.0f);
}

struct Coef { int code; float al, be, de; };

// R13-proven stats+code: psum/psq partials -> serial-warp finalize (bank
// rotation t*65 => conflict-free) -> thread-0 code. All barriers uniform.
__device__ __forceinline__ Coef stats_code(
    const float4* v, int s4, int r, int c4, int t, int p,
    float* ubuf, float* s_q, float* s_m,
    int* s_code, float* s_al, float* s_be, float* s_de,
    const float* __restrict__ r_strong, const float* __restrict__ r_drop,
    const float* __restrict__ r_else,   const float* __restrict__ bright_f,
    const float* __restrict__ contrast_f, const float* __restrict__ slight_f,
    const int* __restrict__ aug_choice, const int* __restrict__ slight_choice)
{
    float* psum = ubuf;
    float* psq  = ubuf + 2080;
#pragma unroll
    for (int k = 0; k < 8; ++k) {
        const int b = 4 * k + s4;
        float s  = (v[k].x + v[k].y) + (v[k].z + v[k].w);
        float ss = fmaf(v[k].x, v[k].x,
                   fmaf(v[k].y, v[k].y,
                   fmaf(v[k].z, v[k].z, v[k].w * v[k].w)));
        psum[b * 65 + r * 4 + c4] = s;
        psq [b * 65 + r * 4 + c4] = ss;
    }
    __syncthreads();

    if (t < NB) {                            // warp 0: batch t (bank-rotated)
        float s = 0.f, ss = 0.f;
#pragma unroll
        for (int j = 0; j < 64; ++j) {
            s  += psum[t * 65 + j];
            ss += psq [t * 65 + j];
        }
        float mean = s * (1.0f / 256.0f);
        float var  = (ss - s * s * (1.0f / 256.0f)) * (1.0f / 255.0f); // ddof=1
        var = fmaxf(var, 0.0f);
        float std_ = sqrtf(var);
        float iq   = 1.0f - 2.0f * fabsf(mean - 0.5f);
        s_q[t] = (std_ + iq + var) * (1.0f / 3.0f);
        s_m[t] = mean;
    }
    __syncthreads();

    if (t == 0) {
        float q = 0.f, m = 0.f;
#pragma unroll
        for (int b = 0; b < NB; ++b) { q += s_q[b]; m += s_m[b]; }
        q *= (1.0f / NB);
        m *= (1.0f / NB);

        bool low    = q < 0.7f;
        bool strong = low  && (r_strong[p] < 0.8f);
        bool drop   = low  && (q < 0.3f) && (r_drop[p] < 0.1f);
        bool els    = !low && (r_else[p] < 0.3f);

        int code = 0;
        if (strong) code = aug_choice[p] + 1;      // 1..4
        if (els)    code = slight_choice[p] + 5;   // 5..6
        if (drop)   code = 7;

        float alpha = 1.f, beta = 0.f, delta = 0.f;
        if      (code == 1) beta = 0.1f;
        else if (code == 3) alpha = bright_f[p];
        else if (code == 4) { float cf = contrast_f[p]; alpha = cf; delta = m * (1.0f - cf); }
        else if (code == 5) beta = 0.05f;
        else if (code == 6) alpha = slight_f[p];
        else if (code == 7) alpha = 0.f;

        *s_code = code; *s_al = alpha; *s_be = beta; *s_de = delta;
    }
    __syncthreads();

    Coef cf;
    cf.code = *s_code; cf.al = *s_al; cf.be = *s_be; cf.de = *s_de;
    return cf;
}

// Affine apply-store for batch chunk [k0,k1). Noise loaded per-k (rare path).
__device__ __forceinline__ void apply_chunk(
    const float4* v, int k0, int k1, const Coef& cf, int s4, int gofs,
    const float* __restrict__ noise, float* __restrict__ out)
{
    if (cf.be != 0.0f) {
#pragma unroll
        for (int k = 0; k < 8; ++k) {
            if (k < k0 || k >= k1) continue;
            float4 n = *reinterpret_cast<const float4*>(
                           noise + (size_t)(4 * k + s4) * IMGSZ + gofs);
            float4 o;
            o.x = clamp01(fmaf(cf.be, n.x, fmaf(cf.al, v[k].x, cf.de)));
            o.y = clamp01(fmaf(cf.be, n.y, fmaf(cf.al, v[k].y, cf.de)));
            o.z = clamp01(fmaf(cf.be, n.z, fmaf(cf.al, v[k].z, cf.de)));
            o.w = clamp01(fmaf(cf.be, n.w, fmaf(cf.al, v[k].w, cf.de)));
            __stcs(reinterpret_cast<float4*>(
                       out + (size_t)(4 * k + s4) * IMGSZ + gofs), o);
        }
    } else {
#pragma unroll
        for (int k = 0; k < 8; ++k) {
            if (k < k0 || k >= k1) continue;
            float4 o;
            o.x = clamp01(fmaf(cf.al, v[k].x, cf.de));
            o.y = clamp01(fmaf(cf.al, v[k].y, cf.de));
            o.z = clamp01(fmaf(cf.al, v[k].z, cf.de));
            o.w = clamp01(fmaf(cf.al, v[k].w, cf.de));
            __stcs(reinterpret_cast<float4*>(
                       out + (size_t)(4 * k + s4) * IMGSZ + gofs), o);
        }
    }
}

// Blur store (CTA-uniform rare path): stage 16 batches at a time via ubuf.
__device__ __forceinline__ void blur_store(
    const float4* v, int s4, int r, int c4, int gofs,
    float* ubuf, float* __restrict__ out)
{
#pragma unroll
    for (int h = 0; h < 2; ++h) {
        __syncthreads();
#pragma unroll
        for (int k = 4 * h; k < 4 * h + 4; ++k) {
            const int bl = (4 * k + s4) - 16 * h;   // 0..15
            *reinterpret_cast<float4*>(ubuf + bl * 320 + r * 20 + c4 * 4) = v[k];
        }
        __syncthreads();
#pragma unroll
        for (int k = 4 * h; k < 4 * h + 4; ++k) {
            const int bl = (4 * k + s4) - 16 * h;
            const float* tb = ubuf + bl * 320;
            float rs[4];
#pragma unroll
            for (int j = 0; j < 4; ++j) {
                const int cc0 = c4 * 4 + j;
                float sum = 0.f;
#pragma unroll
                for (int dy = -1; dy <= 1; ++dy) {
                    const int rr = r + dy;
                    if (rr < 0 || rr >= PS) continue;
#pragma unroll
                    for (int dx = -1; dx <= 1; ++dx) {
                        const int cc = cc0 + dx;
                        if (cc < 0 || cc >= PS) continue;
                        sum += tb[rr * 20 + cc];
                    }
                }
                rs[j] = sum * (1.0f / 9.0f);
            }
            __stcs(reinterpret_cast<float4*>(
                       out + (size_t)(4 * k + s4) * IMGSZ + gofs),
                   make_float4(rs[0], rs[1], rs[2], rs[3]));
        }
    }
}

// ---------------------------------------------------------------------------
// One CTA = TWO adjacent patches, pipelined: P1's loads are issued between
// P0's code computation and P0's stores, so the memory system sees mixed
// read+write traffic instead of alternating bursts (duty-cycle fix).
// Per-patch structure is exactly R13 (best known): thread t owns 16B chunk
// (r = (t>>2)&15, c4 = t&3) of batches 4k+(t>>6), k=0..7, in v[8]/w[8].
// ---------------------------------------------------------------------------
__global__ void __launch_bounds__(256, 3)
fused_kernel(const float* __restrict__ img,
             const float* __restrict__ noise,
             const float* __restrict__ r_strong,
             const float* __restrict__ r_drop,
             const float* __restrict__ r_else,
             const float* __restrict__ bright_f,
             const float* __restrict__ contrast_f,
             const float* __restrict__ slight_f,
             const int*   __restrict__ aug_choice,
             const int*   __restrict__ slight_choice,
             float* __restrict__ out) {
    __shared__ float ubuf[6400];             // stats partials / blur tile
    __shared__ float s_q[NB], s_m[NB];
    __shared__ int   s_code;
    __shared__ float s_al, s_be, s_de;

    const int u    = blockIdx.x;             // 0..2047
    const int p0   = 2 * u;
    const int p1   = p0 + 1;
    const int sy   = p0 >> 6;
    const int px0  = p0 & 63;
    const int t    = threadIdx.x;
    const int c4   = t & 3;
    const int slot = t >> 2;
    const int r    = slot & 15;
    const int s4   = slot >> 4;

    const int gof0 = (sy * PS + r) * 1024 + px0 * PS + c4 * 4;
    const int gof1 = gof0 + PS;              // adjacent patch

    // ---- P0 loads (8 front-batched LDG.128) ----
    float4 v[8];
#pragma unroll
    for (int k = 0; k < 8; ++k)
        v[k] = *reinterpret_cast<const float4*>(
                   img + (size_t)(4 * k + s4) * IMGSZ + gof0);

    // ---- P0 stats + code ----
    Coef c0 = stats_code(v, s4, r, c4, t, p0, ubuf, s_q, s_m,
                         &s_code, &s_al, &s_be, &s_de,
                         r_strong, r_drop, r_else, bright_f, contrast_f,
                         slight_f, aug_choice, slight_choice);

    // ---- pipelined: P1 loads interleaved with P0 stores ----
    float4 w[8];
    if (c0.code != 2) {
#pragma unroll
        for (int k = 0; k < 4; ++k)
            w[k] = *reinterpret_cast<const float4*>(
                       img + (size_t)(4 * k + s4) * IMGSZ + gof1);
        apply_chunk(v, 0, 4, c0, s4, gof0, noise, out);
#pragma unroll
        for (int k = 4; k < 8; ++k)
            w[k] = *reinterpret_cast<const float4*>(
                       img + (size_t)(4 * k + s4) * IMGSZ + gof1);
        apply_chunk(v, 4, 8, c0, s4, gof0, noise, out);
    } else {
#pragma unroll
        for (int k = 0; k < 8; ++k)
            w[k] = *reinterpret_cast<const float4*>(
                       img + (size_t)(4 * k + s4) * IMGSZ + gof1);
        blur_store(v, s4, r, c4, gof0, ubuf, out);
    }
    __syncthreads();                         // ubuf/scalars free for P1

    // ---- P1 stats + code + stores ----
    Coef c1 = stats_code(w, s4, r, c4, t, p1, ubuf, s_q, s_m,
                         &s_code, &s_al, &s_be, &s_de,
                         r_strong, r_drop, r_else, bright_f, contrast_f,
                         slight_f, aug_choice, slight_choice);

    if (c1.code != 2) {
        apply_chunk(w, 0, 8, c1, s4, gof1, noise, out);
    } else {
        blur_store(w, s4, r, c4, gof1, ubuf, out);
    }
}

extern "C" void kernel_launch(void* const* d_in, const int* in_sizes, int n_in,
                              void* d_out, int out_size) {
    const float* img           = (const float*)d_in[0];
    const float* noise         = (const float*)d_in[1];
    const float* r_strong      = (const float*)d_in[2];
    const float* r_drop        = (const float*)d_in[3];
    const float* r_else        = (const float*)d_in[4];
    const float* bright_f      = (const float*)d_in[5];
    const float* contrast_f    = (const float*)d_in[6];
    const float* slight_f      = (const float*)d_in[7];
    const int*   aug_choice    = (const int*)d_in[8];
    const int*   slight_choice = (const int*)d_in[9];
    float* out = (float*)d_out;

    fused_kernel<<<2048, 256>>>(img, noise, r_strong, r_drop, r_else,
                                bright_f, contrast_f, slight_f,
                                aug_choice, slight_choice, out);
}